// round 1
// baseline (speedup 1.0000x reference)
#include <cuda_runtime.h>
#include <cstdint>

// Problem constants
#define IMG     224
#define PATCH   16
#define CHN     3
#define GHN     14          // grid 14x14
#define NPATCH  196
#define NBATCH  64
#define M_DIM   12544       // 64*196
#define K_DIM   3840        // 16*16*15
#define N_DIM   768
#define LN_EPS  1e-5f

// Scratch: gathered patch matrix A[M_DIM][K_DIM], fp32 (~193 MB, static device global)
__device__ float g_patches[(size_t)M_DIM * K_DIM];

// shift table: s=0 identity, then OFFSETS [(0,4),(4,0),(0,-4),(-4,0)] applied as
// shifted(h,w) = x[h-dx, w-dy] if in-bounds else 0
__constant__ int c_dx[5] = {0, 0, 4, 0, -4};
__constant__ int c_dy[5] = {0, 4, 0, -4, 0};

// ---------------------------------------------------------------------------
// Kernel 1: gather shifted patches into row-major A[M_DIM][K_DIM]
//   row = b*196 + gi*14 + gj ; d = (ph*16+pw)*15 + s*3 + c
// Writes coalesced along d; reads hit L2 (x = 38.5MB < L2).
// ---------------------------------------------------------------------------
__global__ __launch_bounds__(256) void gather_kernel(const float* __restrict__ x) {
    size_t idx = (size_t)blockIdx.x * 256 + threadIdx.x;
    if (idx >= (size_t)M_DIM * K_DIM) return;
    int d   = (int)(idx % K_DIM);
    int row = (int)(idx / K_DIM);
    int b = row / NPATCH;
    int n = row % NPATCH;
    int gi = n / GHN, gj = n % GHN;
    int pp = d / 15, c5 = d % 15;
    int ph = pp >> 4, pw = pp & 15;
    int s = c5 / 3, c = c5 % 3;
    int h = gi * PATCH + ph - c_dx[s];
    int w = gj * PATCH + pw - c_dy[s];
    float v = 0.0f;
    if ((unsigned)h < IMG && (unsigned)w < IMG)
        v = x[((size_t)(b * CHN + c) * IMG + (size_t)h) * IMG + w];
    g_patches[idx] = v;
}

// ---------------------------------------------------------------------------
// Kernel 2: C[M,N] = A[M,K] * W[N,K]^T + bias  (both operands K-major: "NT")
// 128x128 tile, BK=16, 256 threads, 8x8 per-thread micro-tile.
// Inner product uses packed fma.rn.f32x2 (2 FMAs/instr) to reach the full
// Blackwell FP32 rate (scalar FFMA is half-rate, rt_SMSP=2).
// ---------------------------------------------------------------------------
#define BM 128
#define BN 128
#define BK 16
#define BMP 132   // padded stride: 16B-aligned rows for LDS.128, reduced store conflicts

__global__ __launch_bounds__(256) void gemm_kernel(const float* __restrict__ W,
                                                   const float* __restrict__ bias,
                                                   float* __restrict__ Cout) {
    __shared__ float As[BK][BMP];
    __shared__ float Bs[BK][BMP];

    const int bn = blockIdx.x;     // 0..5   (N tiles)
    const int bm = blockIdx.y;     // 0..97  (M tiles)
    const int tid = threadIdx.x;
    const int tx = tid & 15;       // 0..15 -> 8 cols each
    const int ty = tid >> 4;       // 0..15 -> 8 rows each

    const float* Ablk = g_patches + (size_t)bm * BM * K_DIM;
    const float* Wblk = W + (size_t)bn * BN * K_DIM;

    // accumulators as packed f32x2 pairs: acc2[i][j] = cols (2j, 2j+1) of row i
    unsigned long long acc2[8][4];
#pragma unroll
    for (int i = 0; i < 8; i++)
#pragma unroll
        for (int j = 0; j < 4; j++) acc2[i][j] = 0ull;

    for (int k0 = 0; k0 < K_DIM; k0 += BK) {
        // cooperative load: 512 float4 per tile per operand; 2 per thread
#pragma unroll
        for (int i = 0; i < 2; i++) {
            int f   = tid + i * 256;       // float4 index 0..511
            int row = f >> 2;              // 0..127
            int kc  = (f & 3) * 4;         // 0,4,8,12
            float4 va = *(const float4*)(Ablk + (size_t)row * K_DIM + k0 + kc);
            As[kc + 0][row] = va.x; As[kc + 1][row] = va.y;
            As[kc + 2][row] = va.z; As[kc + 3][row] = va.w;
            float4 vb = *(const float4*)(Wblk + (size_t)row * K_DIM + k0 + kc);
            Bs[kc + 0][row] = vb.x; Bs[kc + 1][row] = vb.y;
            Bs[kc + 2][row] = vb.z; Bs[kc + 3][row] = vb.w;
        }
        __syncthreads();

#pragma unroll
        for (int k = 0; k < BK; k++) {
            // a: 8 row values, duplicated into both f32x2 lanes
            const float4* ap = (const float4*)&As[k][ty * 8];
            float4 a0 = ap[0], a1 = ap[1];
            unsigned long long a2[8];
            {
                unsigned int au[8];
                au[0] = __float_as_uint(a0.x); au[1] = __float_as_uint(a0.y);
                au[2] = __float_as_uint(a0.z); au[3] = __float_as_uint(a0.w);
                au[4] = __float_as_uint(a1.x); au[5] = __float_as_uint(a1.y);
                au[6] = __float_as_uint(a1.z); au[7] = __float_as_uint(a1.w);
#pragma unroll
                for (int i = 0; i < 8; i++)
                    asm("mov.b64 %0, {%1, %1};" : "=l"(a2[i]) : "r"(au[i]));
            }
            // b: 4 packed pairs read directly as 64-bit (cols 2j,2j+1)
            const unsigned long long* bp =
                (const unsigned long long*)&Bs[k][tx * 8];
            unsigned long long b2[4];
#pragma unroll
            for (int j = 0; j < 4; j++) b2[j] = bp[j];

#pragma unroll
            for (int i = 0; i < 8; i++)
#pragma unroll
                for (int j = 0; j < 4; j++)
                    asm("fma.rn.f32x2 %0, %1, %2, %0;"
                        : "+l"(acc2[i][j]) : "l"(a2[i]), "l"(b2[j]));
        }
        __syncthreads();
    }

    // epilogue: + bias, store
    float* Cblk = Cout + (size_t)(bm * BM) * N_DIM + (size_t)bn * BN;
    const int colbase = bn * BN + tx * 8;
    float bb[8];
#pragma unroll
    for (int j = 0; j < 8; j++) bb[j] = bias[colbase + j];

#pragma unroll
    for (int i = 0; i < 8; i++) {
        int row = ty * 8 + i;
        float* crow = Cblk + (size_t)row * N_DIM + tx * 8;
        float4 o0, o1;
        o0.x = __uint_as_float((unsigned)(acc2[i][0]      )) + bb[0];
        o0.y = __uint_as_float((unsigned)(acc2[i][0] >> 32)) + bb[1];
        o0.z = __uint_as_float((unsigned)(acc2[i][1]      )) + bb[2];
        o0.w = __uint_as_float((unsigned)(acc2[i][1] >> 32)) + bb[3];
        o1.x = __uint_as_float((unsigned)(acc2[i][2]      )) + bb[4];
        o1.y = __uint_as_float((unsigned)(acc2[i][2] >> 32)) + bb[5];
        o1.z = __uint_as_float((unsigned)(acc2[i][3]      )) + bb[6];
        o1.w = __uint_as_float((unsigned)(acc2[i][3] >> 32)) + bb[7];
        ((float4*)crow)[0] = o0;
        ((float4*)crow)[1] = o1;
    }
}

// ---------------------------------------------------------------------------
// Kernel 3: in-place LayerNorm over last dim (768) per row, + gamma/beta
// One CTA per row, 3 elements per thread, population variance (matches jnp.var)
// ---------------------------------------------------------------------------
__global__ __launch_bounds__(256) void ln_kernel(float* __restrict__ h,
                                                 const float* __restrict__ gamma,
                                                 const float* __restrict__ beta) {
    const int row = blockIdx.x;
    float* p = h + (size_t)row * N_DIM;
    const int t = threadIdx.x;

    float v0 = p[t], v1 = p[t + 256], v2 = p[t + 512];
    float s = v0 + v1 + v2;
    float q = v0 * v0 + v1 * v1 + v2 * v2;

#pragma unroll
    for (int o = 16; o > 0; o >>= 1) {
        s += __shfl_down_sync(0xffffffffu, s, o);
        q += __shfl_down_sync(0xffffffffu, q, o);
    }
    __shared__ float ss[8], sq[8];
    if ((t & 31) == 0) { ss[t >> 5] = s; sq[t >> 5] = q; }
    __syncthreads();
    float S = 0.f, Q = 0.f;
#pragma unroll
    for (int i = 0; i < 8; i++) { S += ss[i]; Q += sq[i]; }

    const float mean = S * (1.0f / (float)N_DIM);
    const float var  = Q * (1.0f / (float)N_DIM) - mean * mean;
    const float rstd = rsqrtf(var + LN_EPS);

    p[t]       = (v0 - mean) * rstd * gamma[t]       + beta[t];
    p[t + 256] = (v1 - mean) * rstd * gamma[t + 256] + beta[t + 256];
    p[t + 512] = (v2 - mean) * rstd * gamma[t + 512] + beta[t + 512];
}

// ---------------------------------------------------------------------------
extern "C" void kernel_launch(void* const* d_in, const int* in_sizes, int n_in,
                              void* d_out, int out_size) {
    const float* x     = (const float*)d_in[0];
    const float* pw    = (const float*)d_in[1];
    const float* pb    = (const float*)d_in[2];
    const float* gamma = (const float*)d_in[3];
    const float* beta  = (const float*)d_in[4];
    float* out = (float*)d_out;

    const size_t total = (size_t)M_DIM * K_DIM;
    gather_kernel<<<(unsigned)((total + 255) / 256), 256>>>(x);

    dim3 grid(N_DIM / BN, M_DIM / BM);   // (6, 98)
    gemm_kernel<<<grid, 256>>>(pw, pb, out);

    ln_kernel<<<M_DIM, 256>>>(out, gamma, beta);
}

// round 8
// speedup vs baseline: 4.9043x; 4.9043x over previous
#include <cuda_runtime.h>
#include <cuda_fp16.h>
#include <cstdint>

#define IMG     224
#define PATCH   16
#define CHN     3
#define GHN     14
#define NPATCH  196
#define M_DIM   12544       // 64*196
#define K_DIM   3840        // 16*16*15
#define N_DIM   768
#define LN_EPS  1e-5f

// fp16 scratch: A (96MB) and converted W (5.9MB)
__device__ __half g_A[(size_t)M_DIM * K_DIM];
__device__ __half g_W[(size_t)N_DIM * K_DIM];

__device__ __forceinline__ uint32_t smem_u32(const void* p) {
    return (uint32_t)__cvta_generic_to_shared(p);
}

// ---------------------------------------------------------------------------
// Kernel 1: gather shifted patches -> fp16 A[M][K].  One thread per 16B chunk.
// ---------------------------------------------------------------------------
__global__ __launch_bounds__(256) void gather_f16(const float* __restrict__ x) {
    unsigned chunk = blockIdx.x * 256u + threadIdx.x;   // < 6,021,120
    unsigned row = chunk / 480u;
    unsigned d0  = (chunk - row * 480u) * 8u;
    unsigned b = row / (unsigned)NPATCH;
    unsigned n = row - b * NPATCH;
    int gi = (int)(n / GHN), gj = (int)(n - (n / GHN) * GHN);
    unsigned pp = d0 / 15u;
    int c5 = (int)(d0 - pp * 15u);
    const int baseh = gi * PATCH, basew = gj * PATCH;
    const float* xb = x + (size_t)b * CHN * IMG * IMG;

    union { __half h[8]; uint4 v; } out;
#pragma unroll
    for (int j = 0; j < 8; j++) {
        int s = c5 / 3;
        int c = c5 - 3 * s;
        int ph = (int)(pp >> 4), pw = (int)(pp & 15u);
        int dx = (s == 2) ? 4 : ((s == 4) ? -4 : 0);
        int dy = (s == 1) ? 4 : ((s == 3) ? -4 : 0);
        int h = baseh + ph - dx;
        int w = basew + pw - dy;
        float v = 0.0f;
        if ((unsigned)h < IMG && (unsigned)w < IMG)
            v = xb[c * (IMG * IMG) + h * IMG + w];
        out.h[j] = __float2half(v);
        if (++c5 == 15) { c5 = 0; pp++; }
    }
    *(uint4*)(g_A + (size_t)chunk * 8) = out.v;
}

// ---------------------------------------------------------------------------
// Kernel 1b: convert proj_w (f32) -> g_W (f16)
// ---------------------------------------------------------------------------
__global__ __launch_bounds__(256) void wconv_f16(const float* __restrict__ w) {
    unsigned c = blockIdx.x * 256u + threadIdx.x;       // < 368,640 chunks of 8
    const float4 f0 = *(const float4*)(w + (size_t)c * 8);
    const float4 f1 = *(const float4*)(w + (size_t)c * 8 + 4);
    union { __half h[8]; uint4 v; } out;
    out.h[0] = __float2half(f0.x); out.h[1] = __float2half(f0.y);
    out.h[2] = __float2half(f0.z); out.h[3] = __float2half(f0.w);
    out.h[4] = __float2half(f1.x); out.h[5] = __float2half(f1.y);
    out.h[6] = __float2half(f1.z); out.h[7] = __float2half(f1.w);
    *(uint4*)(g_W + (size_t)c * 8) = out.v;
}

// ---------------------------------------------------------------------------
// Kernel 2: mma.sync GEMM  C[M,768] = A[M,K] * W[768,K]^T  (f16 in, f32 acc)
// BM=128, BN=256, BK=32, 512 threads, 3-stage cp.async pipeline.
// Smem rows padded to 80B -> conflict-free ldmatrix (bank stride 20).
// ---------------------------------------------------------------------------
#define BM 128
#define BN 256
#define BKG 32
#define NSTAGE (K_DIM / BKG)     // 120
#define ROWB   80                // bytes per smem row (64 data + 16 pad)
#define A_SZ   (BM * ROWB)       // 10240
#define B_SZ   (BN * ROWB)       // 20480
#define STG_SZ (A_SZ + B_SZ)     // 30720
#define GEMM_SMEM (3 * STG_SZ)   // 92160

__device__ __forceinline__ void ldsm4(uint32_t addr, uint32_t& r0, uint32_t& r1,
                                      uint32_t& r2, uint32_t& r3) {
    asm volatile("ldmatrix.sync.aligned.m8n8.x4.shared.b16 {%0,%1,%2,%3}, [%4];"
                 : "=r"(r0), "=r"(r1), "=r"(r2), "=r"(r3) : "r"(addr));
}

__device__ __forceinline__ void mma16816(float& c0, float& c1, float& c2, float& c3,
                                         uint32_t a0, uint32_t a1, uint32_t a2, uint32_t a3,
                                         uint32_t b0, uint32_t b1) {
    asm volatile(
        "mma.sync.aligned.m16n8k16.row.col.f32.f16.f16.f32 "
        "{%0,%1,%2,%3}, {%4,%5,%6,%7}, {%8,%9}, {%0,%1,%2,%3};"
        : "+f"(c0), "+f"(c1), "+f"(c2), "+f"(c3)
        : "r"(a0), "r"(a1), "r"(a2), "r"(a3), "r"(b0), "r"(b1));
}

__global__ __launch_bounds__(512, 1) void gemm_hmma(float* __restrict__ Cout) {
    extern __shared__ char smem[];
    const uint32_t sb = smem_u32(smem);
    const int tid = threadIdx.x;
    const int bn = blockIdx.x;            // 0..2
    const int bm = blockIdx.y;            // 0..97
    const int wid = tid >> 5, lane = tid & 31;
    const int wm = wid >> 3;              // 0..1  (64 rows each)
    const int wn = wid & 7;               // 0..7  (32 cols each)

    const __half* Ab = g_A + (size_t)bm * BM * K_DIM;
    const __half* Wb = g_W + (size_t)bn * BN * K_DIM;

    // fill one stage: A 512 chunks (1/thread), B 1024 chunks (2/thread)
#define FILL(buf, k0) do {                                                       \
    uint32_t _as = sb + (buf) * STG_SZ;                                          \
    { int _r = tid >> 2, _c = tid & 3;                                           \
      asm volatile("cp.async.cg.shared.global [%0], [%1], 16;"                   \
        :: "r"(_as + _r * ROWB + _c * 16),                                       \
           "l"((const void*)(Ab + (size_t)_r * K_DIM + (k0) + _c * 8))); }       \
    uint32_t _bs = _as + A_SZ;                                                   \
    _Pragma("unroll")                                                            \
    for (int _i = 0; _i < 2; _i++) {                                             \
        int _id = tid + _i * 512; int _r = _id >> 2, _c = _id & 3;               \
        asm volatile("cp.async.cg.shared.global [%0], [%1], 16;"                 \
          :: "r"(_bs + _r * ROWB + _c * 16),                                     \
             "l"((const void*)(Wb + (size_t)_r * K_DIM + (k0) + _c * 8)));       \
    }                                                                            \
    asm volatile("cp.async.commit_group;");                                      \
} while (0)

    FILL(0, 0); FILL(1, BKG); FILL(2, 2 * BKG);

    float acc[4][4][4];
#pragma unroll
    for (int i = 0; i < 4; i++)
#pragma unroll
        for (int j = 0; j < 4; j++)
#pragma unroll
            for (int q = 0; q < 4; q++) acc[i][j][q] = 0.0f;

    const int lrow = lane & 15;           // ldmatrix row select
    const int lhalf = lane >> 4;          // k-half select (0/1) -> +16B

    for (int s = 0; s < NSTAGE; s++) {
        asm volatile("cp.async.wait_group 2;");
        __syncthreads();
        const int buf = s - (s / 3) * 3;
        const uint32_t as = sb + buf * STG_SZ;
        const uint32_t bs = as + A_SZ;

#pragma unroll
        for (int ks = 0; ks < 2; ks++) {
            // A frags: 4 m-tiles of 16x16
            uint32_t a[4][4];
#pragma unroll
            for (int mt = 0; mt < 4; mt++) {
                uint32_t ad = as + (uint32_t)(wm * 64 + mt * 16 + lrow) * ROWB
                              + ks * 32 + lhalf * 16;
                ldsm4(ad, a[mt][0], a[mt][1], a[mt][2], a[mt][3]);
            }
            // B frags: 2 groups of 16 n-rows x 16 k
            uint32_t bg[2][4];
#pragma unroll
            for (int g = 0; g < 2; g++) {
                uint32_t bd = bs + (uint32_t)(wn * 32 + g * 16 + lrow) * ROWB
                              + ks * 32 + lhalf * 16;
                ldsm4(bd, bg[g][0], bg[g][1], bg[g][2], bg[g][3]);
            }
#pragma unroll
            for (int mt = 0; mt < 4; mt++)
#pragma unroll
                for (int nt = 0; nt < 4; nt++) {
                    const int g = nt >> 1, pr = nt & 1;
                    mma16816(acc[mt][nt][0], acc[mt][nt][1], acc[mt][nt][2], acc[mt][nt][3],
                             a[mt][0], a[mt][1], a[mt][2], a[mt][3],
                             bg[g][pr], bg[g][pr + 2]);
                }
        }
        __syncthreads();
        if (s + 3 < NSTAGE) {
            FILL(buf, (s + 3) * BKG);
        } else {
            asm volatile("cp.async.commit_group;");
        }
    }

    // epilogue: direct register -> gmem stores (float2 per acc pair)
    const int mbase = bm * BM + wm * 64 + (lane >> 2);
    const int nbase = bn * BN + wn * 32 + 2 * (lane & 3);
#pragma unroll
    for (int mt = 0; mt < 4; mt++) {
#pragma unroll
        for (int nt = 0; nt < 4; nt++) {
            float2 v0 = make_float2(acc[mt][nt][0], acc[mt][nt][1]);
            float2 v1 = make_float2(acc[mt][nt][2], acc[mt][nt][3]);
            *(float2*)(Cout + (size_t)(mbase + mt * 16) * N_DIM + nbase + nt * 8) = v0;
            *(float2*)(Cout + (size_t)(mbase + mt * 16 + 8) * N_DIM + nbase + nt * 8) = v1;
        }
    }
}

// ---------------------------------------------------------------------------
// Kernel 3: LayerNorm (adds proj bias first), in-place on d_out
// ---------------------------------------------------------------------------
__global__ __launch_bounds__(256) void ln_kernel(float* __restrict__ hbuf,
                                                 const float* __restrict__ pbias,
                                                 const float* __restrict__ gamma,
                                                 const float* __restrict__ beta) {
    const int row = blockIdx.x;
    float* p = hbuf + (size_t)row * N_DIM;
    const int t = threadIdx.x;

    float v0 = p[t] + pbias[t];
    float v1 = p[t + 256] + pbias[t + 256];
    float v2 = p[t + 512] + pbias[t + 512];
    float s = v0 + v1 + v2;
    float q = v0 * v0 + v1 * v1 + v2 * v2;

#pragma unroll
    for (int o = 16; o > 0; o >>= 1) {
        s += __shfl_down_sync(0xffffffffu, s, o);
        q += __shfl_down_sync(0xffffffffu, q, o);
    }
    __shared__ float ss[8], sq[8];
    if ((t & 31) == 0) { ss[t >> 5] = s; sq[t >> 5] = q; }
    __syncthreads();
    float S = 0.f, Q = 0.f;
#pragma unroll
    for (int i = 0; i < 8; i++) { S += ss[i]; Q += sq[i]; }

    const float mean = S * (1.0f / (float)N_DIM);
    const float var  = Q * (1.0f / (float)N_DIM) - mean * mean;
    const float rstd = rsqrtf(var + LN_EPS);

    p[t]       = (v0 - mean) * rstd * gamma[t]       + beta[t];
    p[t + 256] = (v1 - mean) * rstd * gamma[t + 256] + beta[t + 256];
    p[t + 512] = (v2 - mean) * rstd * gamma[t + 512] + beta[t + 512];
}

// ---------------------------------------------------------------------------
extern "C" void kernel_launch(void* const* d_in, const int* in_sizes, int n_in,
                              void* d_out, int out_size) {
    const float* x     = (const float*)d_in[0];
    const float* pw    = (const float*)d_in[1];
    const float* pb    = (const float*)d_in[2];
    const float* gamma = (const float*)d_in[3];
    const float* beta  = (const float*)d_in[4];
    float* out = (float*)d_out;

    cudaFuncSetAttribute(gemm_hmma,
                         cudaFuncAttributeMaxDynamicSharedMemorySize, GEMM_SMEM);

    gather_f16<<<23520, 256>>>(x);                 // 6,021,120 chunks
    wconv_f16<<<1440, 256>>>(pw);                  // 368,640 chunks

    dim3 grid(N_DIM / BN, M_DIM / BM);             // (3, 98)
    gemm_hmma<<<grid, 512, GEMM_SMEM>>>(out);

    ln_kernel<<<M_DIM, 256>>>(out, pb, gamma, beta);
}